// round 12
// baseline (speedup 1.0000x reference)
#include <cuda_runtime.h>
#include <stdint.h>

#define FULLMASK 0xFFFFFFFFu
#define NBATCH 16
#define NPT 2048
#define KNNK 20
#define EPSV 1e-5f
#define NEGINF (__int_as_float(0xff800000))

typedef unsigned long long u64;

// scratch (device globals: no allocation allowed)
__device__ float g_Ys[NBATCH * NPT * 32];
__device__ float g_Ps[NBATCH * NPT * 32];
__device__ int   g_knn[NBATCH * NPT * KNNK];

// ---- packed f32x2 helpers ----
__device__ __forceinline__ u64 pack2(float a, float b) {
    u64 r; asm("mov.b64 %0, {%1, %2};" : "=l"(r) : "f"(a), "f"(b)); return r;
}
__device__ __forceinline__ void unpack2(u64 v, float& a, float& b) {
    asm("mov.b64 {%0, %1}, %2;" : "=f"(a), "=f"(b) : "l"(v));
}
__device__ __forceinline__ u64 fma2(u64 a, u64 b, u64 c) {
    u64 d; asm("fma.rn.f32x2 %0, %1, %2, %3;" : "=l"(d) : "l"(a), "l"(b), "l"(c)); return d;
}
__device__ __forceinline__ u64 mul2(u64 a, u64 b) {
    u64 d; asm("mul.rn.f32x2 %0, %1, %2;" : "=l"(d) : "l"(a), "l"(b)); return d;
}
__device__ __forceinline__ u64 add2(u64 a, u64 b) {
    u64 d; asm("add.rn.f32x2 %0, %1, %2;" : "=l"(d) : "l"(a), "l"(b)); return d;
}

// monotone u32 transform of float (order-preserving)
__device__ __forceinline__ unsigned monot(float v) {
    unsigned u = __float_as_uint(v);
    return u ^ ((unsigned)(((int)u) >> 31) | 0x80000000u);
}

// values-only sorted-desc top-3 insert: pure min/max network (5 FMNMX)
__device__ __forceinline__ void ins3v(float& v1, float& v2, float& v3, float pd) {
    float u1 = fminf(v1, pd); v1 = fmaxf(v1, pd);
    float u2 = fminf(v2, u1); v2 = fmaxf(v2, u1);
    v3 = fmaxf(v3, u2);
}

// ---- KNN: warp/row. Phase1: value-only scan. Phase2: REDUX select v20.
//      Phase3: threshold collect with index recovery (order-free output). ----
__global__ __launch_bounds__(256) void knn_kernel(const float* __restrict__ xyz) {
    __shared__ __align__(16) float sx[NPT], sy[NPT], sz[NPT], snw[NPT];
    __shared__ int eqbuf[8][16];
    __shared__ int ctrs[8][2];   // [warp][0]=gt count, [1]=eq count
    int b = blockIdx.x >> 6;          // 64 blocks per batch
    int chunk = blockIdx.x & 63;      // 32 rows per block
    const float* xb = xyz + (size_t)b * 3 * NPT;
    for (int i = threadIdx.x; i < NPT; i += 256) {
        float x = xb[i], y = xb[NPT + i], z = xb[2 * NPT + i];
        sx[i] = x; sy[i] = y; sz[i] = z;
        snw[i] = -(x * x + y * y + z * z);
    }
    __syncthreads();
    int warp = threadIdx.x >> 5, lane = threadIdx.x & 31;
    const u64 two2 = pack2(2.0f, 2.0f);
    #pragma unroll 1
    for (int rr = 0; rr < 4; rr++) {
        int n = chunk * 32 + warp * 4 + rr;
        float cx = sx[n], cy = sy[n], cz = sz[n];
        u64 cx2 = pack2(cx, cx), cy2 = pack2(cy, cy), cz2 = pack2(cz, cz);
        u64 bb2 = pack2(snw[n], snw[n]);
        // ---- phase 1: values-only dual top-3 (even j -> A, odd j -> B) ----
        float va1 = NEGINF, va2 = NEGINF, va3 = NEGINF;
        float vb1 = NEGINF, vb2 = NEGINF, vb3 = NEGINF;
        #pragma unroll 4
        for (int t = 0; t < 32; t++) {
            int jj = t * 64 + 2 * lane;
            u64 px = *(const u64*)(sx + jj);
            u64 py = *(const u64*)(sy + jj);
            u64 pz = *(const u64*)(sz + jj);
            u64 pw = *(const u64*)(snw + jj);
            u64 dot2 = fma2(cz2, pz, fma2(cy2, py, mul2(cx2, px)));
            u64 pd2 = fma2(two2, dot2, add2(pw, bb2));  // 2*dot - xx_i - xx_j
            float pl, ph; unpack2(pd2, pl, ph);
            ins3v(va1, va2, va3, pl);
            ins3v(vb1, vb2, vb3, ph);
        }
        // ---- phase 2: 20 REDUX rounds -> v20f (20th largest, with multiplicity) ----
        float v20f = 0.f;
        #pragma unroll 1
        for (int r = 0; r < KNNK; r++) {
            float v1 = fmaxf(va1, vb1);
            unsigned key = monot(v1);
            unsigned mx = __reduce_max_sync(FULLMASK, key);
            unsigned ball = __ballot_sync(FULLMASK, key == mx);
            int wl = __ffs(ball) - 1;          // unique winner lane
            if (r == KNNK - 1) { v20f = __shfl_sync(FULLMASK, v1, wl); break; }
            bool win = (lane == wl);
            bool pA = (va1 >= vb1);
            bool popA = win && pA, popB = win && !pA;
            va1 = popA ? va2 : va1; va2 = popA ? va3 : va2; va3 = popA ? NEGINF : va3;
            vb1 = popB ? vb2 : vb1; vb2 = popB ? vb3 : vb2; vb3 = popB ? NEGINF : vb3;
            // refill a list when it empties: all its values > v1 already emitted
            if (popA && va1 == NEGINF) {   // ~2% of rows
                #pragma unroll 4
                for (int t = 0; t < 32; t++) {
                    int jj = t * 64 + 2 * lane;
                    u64 px = *(const u64*)(sx + jj);
                    u64 py = *(const u64*)(sy + jj);
                    u64 pz = *(const u64*)(sz + jj);
                    u64 pw = *(const u64*)(snw + jj);
                    u64 dot2 = fma2(cz2, pz, fma2(cy2, py, mul2(cx2, px)));
                    u64 pd2 = fma2(two2, dot2, add2(pw, bb2));
                    float pl, ph; unpack2(pd2, pl, ph);
                    (void)ph;
                    ins3v(va1, va2, va3, (pl < v1) ? pl : NEGINF);
                }
            }
            if (popB && vb1 == NEGINF) {
                #pragma unroll 4
                for (int t = 0; t < 32; t++) {
                    int jj = t * 64 + 2 * lane;
                    u64 px = *(const u64*)(sx + jj);
                    u64 py = *(const u64*)(sy + jj);
                    u64 pz = *(const u64*)(sz + jj);
                    u64 pw = *(const u64*)(snw + jj);
                    u64 dot2 = fma2(cz2, pz, fma2(cy2, py, mul2(cx2, px)));
                    u64 pd2 = fma2(two2, dot2, add2(pw, bb2));
                    float pl, ph; unpack2(pd2, pl, ph);
                    (void)pl;
                    ins3v(vb1, vb2, vb3, (ph < v1) ? ph : NEGINF);
                }
            }
        }
        // ---- phase 3: collect indices (order-free; jax tie rule at boundary) ----
        if (lane == 0) { ctrs[warp][0] = 0; ctrs[warp][1] = 0; }
        __syncwarp();
        int base = (b * NPT + n) * KNNK;
        #pragma unroll 4
        for (int t = 0; t < 32; t++) {
            int jj = t * 64 + 2 * lane;
            u64 px = *(const u64*)(sx + jj);
            u64 py = *(const u64*)(sy + jj);
            u64 pz = *(const u64*)(sz + jj);
            u64 pw = *(const u64*)(snw + jj);
            u64 dot2 = fma2(cz2, pz, fma2(cy2, py, mul2(cx2, px)));
            u64 pd2 = fma2(two2, dot2, add2(pw, bb2));   // bit-identical to phase 1
            float pl, ph; unpack2(pd2, pl, ph);
            if (pl >= v20f || ph >= v20f) {   // single rare branch region
                if (pl > v20f) { int p = atomicAdd(&ctrs[warp][0], 1); g_knn[base + p] = jj; }
                else if (pl == v20f) { int p = atomicAdd(&ctrs[warp][1], 1); if (p < 16) eqbuf[warp][p] = jj; }
                if (ph > v20f) { int p = atomicAdd(&ctrs[warp][0], 1); g_knn[base + p] = jj + 1; }
                else if (ph == v20f) { int p = atomicAdd(&ctrs[warp][1], 1); if (p < 16) eqbuf[warp][p] = jj + 1; }
            }
        }
        __syncwarp();
        int m = ctrs[warp][0], e = ctrs[warp][1];
        int need = KNNK - m;
        if (e == need) {                         // common: take all eq entries
            if (lane < need) g_knn[base + m + lane] = eqbuf[warp][lane];
        } else {                                 // rare value-tie at boundary:
            int myv = (lane < e && lane < 16) ? eqbuf[warp][lane] : 0x7FFFFFFF;
            #pragma unroll 1
            for (int t2 = 0; t2 < need; t2++) {  // smallest indices win (jax stable)
                unsigned mn = __reduce_min_sync(FULLMASK, (unsigned)myv);
                if ((unsigned)myv == mn) myv = 0x7FFFFFFF;
                if (lane == 0) g_knn[base + m + t2] = (int)mn;
            }
        }
        __syncwarp();
    }
}

// --- precompute: smem-staged xf tile; Ys = s1*(W1a xf), Ps = s1*((W1b-W1a) xf)+shift1 ---
__global__ __launch_bounds__(256) void pre_kernel(
    const float* __restrict__ xf, const float* __restrict__ W1,
    const float* __restrict__ g1, const float* __restrict__ b1,
    const float* __restrict__ m1, const float* __restrict__ v1) {
    __shared__ float W1T[128 * 32];   // [c][o] transposed for conflict-free LDS
    __shared__ float xtile[64][64];   // [c][nn]: 64 channels x 64 points, coalesced fill
    int bq = blockIdx.x >> 5;         // batch (32 blocks per batch)
    int n0 = (blockIdx.x & 31) * 64;  // first point of this block
    for (int i = threadIdx.x; i < 4096; i += 256) {
        int o = i & 31, cc = i >> 5;
        W1T[cc * 32 + o] = W1[o * 128 + cc];
    }
    const float* xfb = xf + (size_t)bq * 64 * NPT + n0;
    for (int i = threadIdx.x; i < 4096; i += 256) {
        int cc = i >> 6, nn = i & 63;
        xtile[cc][nn] = xfb[(size_t)cc * NPT + nn];   // coalesced 64-float rows
    }
    __syncthreads();
    int warp = threadIdx.x >> 5, lane = threadIdx.x & 31;
    float s = g1[lane] * rsqrtf(v1[lane] + EPSV);
    float shift = fmaf(-m1[lane], s, b1[lane]);
    #pragma unroll 1
    for (int pp = 0; pp < 8; pp++) {
        int nn = warp * 8 + pp;
        int point = bq * NPT + n0 + nn;
        float y = 0.f, p = 0.f;
        #pragma unroll
        for (int cc = 0; cc < 64; cc++) {
            float xv = xtile[cc][nn];               // smem broadcast
            float wa = W1T[cc * 32 + lane];         // W1[:,0:64]  (nbr - x part)
            float wb = W1T[(cc + 64) * 32 + lane];  // W1[:,64:128] (x part)
            y = fmaf(wa, xv, y);
            p = fmaf(wb - wa, xv, p);
        }
        g_Ys[point * 32 + lane] = y * s;
        g_Ps[point * 32 + lane] = fmaf(p, s, shift);
    }
}

// ---- edge MLP: warp per 4 points, double-buffered smem, ONE syncwarp per k ----
__global__ __launch_bounds__(128) void mlp_kernel(
    const float* __restrict__ W2, const float* __restrict__ g2,
    const float* __restrict__ b2, const float* __restrict__ m2,
    const float* __restrict__ v2, const float* __restrict__ W3,
    float* __restrict__ out) {
    __shared__ float W2T[1024];   // [c][o], BN2 scale folded
    __shared__ float W3T[2048];   // [c][o]
    __shared__ float sh2s[32];
    __shared__ __align__(16) float hbuf[4][2][4][32];   // [warp][buf][pt][lane]
    __shared__ __align__(16) float fbuf[4][2][4][32];
    for (int i = threadIdx.x; i < 1024; i += 128) {
        int o = i & 31, cc = i >> 5;
        float s2 = g2[o] * rsqrtf(v2[o] + EPSV);
        W2T[cc * 32 + o] = W2[o * 32 + cc] * s2;
    }
    for (int i = threadIdx.x; i < 2048; i += 128) {
        int o = i & 63, cc = i >> 6;
        W3T[cc * 64 + o] = W3[o * 32 + cc];
    }
    if (threadIdx.x < 32) {
        int o = threadIdx.x;
        float s2 = g2[o] * rsqrtf(v2[o] + EPSV);
        sh2s[o] = fmaf(-m2[o], s2, b2[o]);
    }
    __syncthreads();
    int warp = threadIdx.x >> 5, lane = threadIdx.x & 31;
    // pre-packed weight pairs (consecutive input channels -> f32x2 lanes)
    u64 w2p[16], w3ap[16], w3bp[16];
    #pragma unroll
    for (int q = 0; q < 16; q++) {
        w2p[q]  = pack2(W2T[(2 * q) * 32 + lane],      W2T[(2 * q + 1) * 32 + lane]);
        w3ap[q] = pack2(W3T[(2 * q) * 64 + lane],      W3T[(2 * q + 1) * 64 + lane]);
        w3bp[q] = pack2(W3T[(2 * q) * 64 + 32 + lane], W3T[(2 * q + 1) * 64 + 32 + lane]);
    }
    float sh2 = sh2s[lane];
    #pragma unroll 1
    for (int pp = 0; pp < 2; pp++) {
        int p0 = (blockIdx.x * 4 + warp) * 8 + 4 * pp;  // 4 consecutive points
        int b = p0 >> 11, n0 = p0 & (NPT - 1);
        const float* YsB = g_Ys + (size_t)b * NPT * 32;
        float ps[4], ysn[4];
        int idx[4];
        #pragma unroll
        for (int u = 0; u < 4; u++) {
            ps[u] = g_Ps[(p0 + u) * 32 + lane];
            idx[u] = (lane < KNNK) ? g_knn[(p0 + u) * KNNK + lane] : 0;
        }
        #pragma unroll
        for (int u = 0; u < 4; u++) {
            int j = __shfl_sync(FULLMASK, idx[u], 0);
            ysn[u] = YsB[j * 32 + lane];
        }
        // prologue: h_0 into buffer 0
        #pragma unroll
        for (int u = 0; u < 4; u++) {
            float h = ysn[u] + ps[u];
            int jn = __shfl_sync(FULLMASK, idx[u], 1);
            ysn[u] = YsB[jn * 32 + lane];            // prefetch for k=1
            hbuf[warp][0][u][lane] = fmaxf(h, 0.2f * h);
        }
        __syncwarp();
        float a0[4], a1[4];
        #pragma unroll
        for (int u = 0; u < 4; u++) { a0[u] = NEGINF; a1[u] = NEGINF; }
        #pragma unroll 1
        for (int k = 0; k < KNNK; k++) {
            int cur = k & 1, nxt = cur ^ 1;
            const float4* hb = (const float4*)hbuf[warp][cur];
            const float4* fb = (const float4*)fbuf[warp][cur];
            // layer2 from h_k
            u64 acc[4] = {0, 0, 0, 0};
            #pragma unroll
            for (int q = 0; q < 8; q++) {
                #pragma unroll
                for (int u = 0; u < 4; u++) {
                    float4 hv = hb[u * 8 + q];
                    acc[u] = fma2(w2p[2 * q],     pack2(hv.x, hv.y), acc[u]);
                    acc[u] = fma2(w2p[2 * q + 1], pack2(hv.z, hv.w), acc[u]);
                }
            }
            #pragma unroll
            for (int u = 0; u < 4; u++) {
                float ax, ay;
                unpack2(acc[u], ax, ay);
                float f = ax + ay + sh2;
                fbuf[warp][cur][u][lane] = fmaxf(f, 0.2f * f);
            }
            // compute h_{k+1} into the other buffer (before the single sync)
            if (k + 1 < KNNK) {
                #pragma unroll
                for (int u = 0; u < 4; u++) {
                    float h = ysn[u] + ps[u];
                    if (k + 2 < KNNK) {
                        int jn = __shfl_sync(FULLMASK, idx[u], k + 2);
                        ysn[u] = YsB[jn * 32 + lane];
                    }
                    hbuf[warp][nxt][u][lane] = fmaxf(h, 0.2f * h);
                }
            }
            __syncwarp();   // the ONLY sync per k
            // layer3 from f2_k, running max
            u64 t0[4] = {0, 0, 0, 0}, t1[4] = {0, 0, 0, 0};
            #pragma unroll
            for (int q = 0; q < 8; q++) {
                #pragma unroll
                for (int u = 0; u < 4; u++) {
                    float4 fv = fb[u * 8 + q];
                    u64 lo = pack2(fv.x, fv.y), hi = pack2(fv.z, fv.w);
                    t0[u] = fma2(w3ap[2 * q], lo, t0[u]);
                    t1[u] = fma2(w3bp[2 * q], lo, t1[u]);
                    t0[u] = fma2(w3ap[2 * q + 1], hi, t0[u]);
                    t1[u] = fma2(w3bp[2 * q + 1], hi, t1[u]);
                }
            }
            #pragma unroll
            for (int u = 0; u < 4; u++) {
                float x0, y0, x1, y1;
                unpack2(t0[u], x0, y0);
                unpack2(t1[u], x1, y1);
                a0[u] = fmaxf(a0[u], x0 + y0);
                a1[u] = fmaxf(a1[u], x1 + y1);
            }
        }
        // out[b][c][2n+u']: 4 adjacent points -> two 16B stores (n0 % 4 == 0)
        float* obase = out + (size_t)(b * 32 + lane) * (2 * NPT) + 2 * n0;
        ((float4*)obase)[0] = make_float4(a0[0], a1[0], a0[1], a1[1]);
        ((float4*)obase)[1] = make_float4(a0[2], a1[2], a0[3], a1[3]);
    }
}

extern "C" void kernel_launch(void* const* d_in, const int* in_sizes, int n_in,
                              void* d_out, int out_size) {
    const float* xyz = (const float*)d_in[0];
    const float* xf  = (const float*)d_in[1];
    const float* W1  = (const float*)d_in[2];
    const float* g1  = (const float*)d_in[3];
    const float* b1  = (const float*)d_in[4];
    const float* m1  = (const float*)d_in[5];
    const float* v1  = (const float*)d_in[6];
    const float* W2  = (const float*)d_in[7];
    const float* g2  = (const float*)d_in[8];
    const float* b2  = (const float*)d_in[9];
    const float* m2  = (const float*)d_in[10];
    const float* v2  = (const float*)d_in[11];
    const float* W3  = (const float*)d_in[12];
    float* out = (float*)d_out;

    knn_kernel<<<1024, 256>>>(xyz);
    pre_kernel<<<512, 256>>>(xf, W1, g1, b1, m1, v1);
    mlp_kernel<<<1024, 128>>>(W2, g2, b2, m2, v2, W3, out);
}

// round 13
// speedup vs baseline: 1.0851x; 1.0851x over previous
#include <cuda_runtime.h>
#include <stdint.h>

#define FULLMASK 0xFFFFFFFFu
#define NBATCH 16
#define NPT 2048
#define KNNK 20
#define EPSV 1e-5f
#define NEGINF (__int_as_float(0xff800000))

typedef unsigned long long u64;

// scratch (device globals: no allocation allowed)
__device__ float g_Ys[NBATCH * NPT * 32];
__device__ float g_Ps[NBATCH * NPT * 32];
__device__ int   g_knn[NBATCH * NPT * KNNK];

// ---- packed f32x2 helpers ----
__device__ __forceinline__ u64 pack2(float a, float b) {
    u64 r; asm("mov.b64 %0, {%1, %2};" : "=l"(r) : "f"(a), "f"(b)); return r;
}
__device__ __forceinline__ void unpack2(u64 v, float& a, float& b) {
    asm("mov.b64 {%0, %1}, %2;" : "=f"(a), "=f"(b) : "l"(v));
}
__device__ __forceinline__ u64 fma2(u64 a, u64 b, u64 c) {
    u64 d; asm("fma.rn.f32x2 %0, %1, %2, %3;" : "=l"(d) : "l"(a), "l"(b), "l"(c)); return d;
}
__device__ __forceinline__ u64 mul2(u64 a, u64 b) {
    u64 d; asm("mul.rn.f32x2 %0, %1, %2;" : "=l"(d) : "l"(a), "l"(b)); return d;
}
__device__ __forceinline__ u64 add2(u64 a, u64 b) {
    u64 d; asm("add.rn.f32x2 %0, %1, %2;" : "=l"(d) : "l"(a), "l"(b)); return d;
}

// monotone u32 transform of float (order-preserving)
__device__ __forceinline__ unsigned monot(float v) {
    unsigned u = __float_as_uint(v);
    return u ^ ((unsigned)(((int)u) >> 31) | 0x80000000u);
}

// values-only sorted-desc top-3 insert: pure min/max network (5 FMNMX)
__device__ __forceinline__ void ins3v(float& v1, float& v2, float& v3, float pd) {
    float u1 = fminf(v1, pd); v1 = fmaxf(v1, pd);
    float u2 = fminf(v2, u1); v2 = fmaxf(v2, u1);
    v3 = fmaxf(v3, u2);
}

// ---- KNN: warp/row. Phase1: value-only scan. Phase2: REDUX select v20.
//      Phase3: threshold collect with index recovery (order-free output). ----
__global__ __launch_bounds__(256) void knn_kernel(const float* __restrict__ xyz) {
    __shared__ __align__(16) float sx[NPT], sy[NPT], sz[NPT], snw[NPT];
    __shared__ int eqbuf[8][16];
    __shared__ int ctrs[8][2];   // [warp][0]=gt count, [1]=eq count
    int b = blockIdx.x >> 6;          // 64 blocks per batch
    int chunk = blockIdx.x & 63;      // 32 rows per block
    const float* xb = xyz + (size_t)b * 3 * NPT;
    for (int i = threadIdx.x; i < NPT; i += 256) {
        float x = xb[i], y = xb[NPT + i], z = xb[2 * NPT + i];
        sx[i] = x; sy[i] = y; sz[i] = z;
        snw[i] = -(x * x + y * y + z * z);
    }
    __syncthreads();
    int warp = threadIdx.x >> 5, lane = threadIdx.x & 31;
    const u64 two2 = pack2(2.0f, 2.0f);
    #pragma unroll 1
    for (int rr = 0; rr < 4; rr++) {
        int n = chunk * 32 + warp * 4 + rr;
        float cx = sx[n], cy = sy[n], cz = sz[n];
        u64 cx2 = pack2(cx, cx), cy2 = pack2(cy, cy), cz2 = pack2(cz, cz);
        u64 bb2 = pack2(snw[n], snw[n]);
        // ---- phase 1: values-only dual top-3 (even j -> A, odd j -> B) ----
        float va1 = NEGINF, va2 = NEGINF, va3 = NEGINF;
        float vb1 = NEGINF, vb2 = NEGINF, vb3 = NEGINF;
        #pragma unroll 4
        for (int t = 0; t < 32; t++) {
            int jj = t * 64 + 2 * lane;
            u64 px = *(const u64*)(sx + jj);
            u64 py = *(const u64*)(sy + jj);
            u64 pz = *(const u64*)(sz + jj);
            u64 pw = *(const u64*)(snw + jj);
            u64 dot2 = fma2(cz2, pz, fma2(cy2, py, mul2(cx2, px)));
            u64 pd2 = fma2(two2, dot2, add2(pw, bb2));  // 2*dot - xx_i - xx_j
            float pl, ph; unpack2(pd2, pl, ph);
            ins3v(va1, va2, va3, pl);
            ins3v(vb1, vb2, vb3, ph);
        }
        // ---- phase 2: 20 REDUX rounds -> v20f (20th largest, with multiplicity) ----
        float v20f = 0.f;
        #pragma unroll 1
        for (int r = 0; r < KNNK; r++) {
            float v1 = fmaxf(va1, vb1);
            unsigned key = monot(v1);
            unsigned mx = __reduce_max_sync(FULLMASK, key);
            unsigned ball = __ballot_sync(FULLMASK, key == mx);
            int wl = __ffs(ball) - 1;          // unique winner lane
            if (r == KNNK - 1) { v20f = __shfl_sync(FULLMASK, v1, wl); break; }
            bool win = (lane == wl);
            bool pA = (va1 >= vb1);
            bool popA = win && pA, popB = win && !pA;
            va1 = popA ? va2 : va1; va2 = popA ? va3 : va2; va3 = popA ? NEGINF : va3;
            vb1 = popB ? vb2 : vb1; vb2 = popB ? vb3 : vb2; vb3 = popB ? NEGINF : vb3;
            // refill a list when it empties: all its values > v1 already emitted
            if (popA && va1 == NEGINF) {   // ~2% of rows
                #pragma unroll 4
                for (int t = 0; t < 32; t++) {
                    int jj = t * 64 + 2 * lane;
                    u64 px = *(const u64*)(sx + jj);
                    u64 py = *(const u64*)(sy + jj);
                    u64 pz = *(const u64*)(sz + jj);
                    u64 pw = *(const u64*)(snw + jj);
                    u64 dot2 = fma2(cz2, pz, fma2(cy2, py, mul2(cx2, px)));
                    u64 pd2 = fma2(two2, dot2, add2(pw, bb2));
                    float pl, ph; unpack2(pd2, pl, ph);
                    (void)ph;
                    ins3v(va1, va2, va3, (pl < v1) ? pl : NEGINF);
                }
            }
            if (popB && vb1 == NEGINF) {
                #pragma unroll 4
                for (int t = 0; t < 32; t++) {
                    int jj = t * 64 + 2 * lane;
                    u64 px = *(const u64*)(sx + jj);
                    u64 py = *(const u64*)(sy + jj);
                    u64 pz = *(const u64*)(sz + jj);
                    u64 pw = *(const u64*)(snw + jj);
                    u64 dot2 = fma2(cz2, pz, fma2(cy2, py, mul2(cx2, px)));
                    u64 pd2 = fma2(two2, dot2, add2(pw, bb2));
                    float pl, ph; unpack2(pd2, pl, ph);
                    (void)pl;
                    ins3v(vb1, vb2, vb3, (ph < v1) ? ph : NEGINF);
                }
            }
        }
        // ---- phase 3: collect indices (order-free; jax tie rule at boundary) ----
        if (lane == 0) { ctrs[warp][0] = 0; ctrs[warp][1] = 0; }
        __syncwarp();
        int base = (b * NPT + n) * KNNK;
        #pragma unroll 4
        for (int t = 0; t < 32; t++) {
            int jj = t * 64 + 2 * lane;
            u64 px = *(const u64*)(sx + jj);
            u64 py = *(const u64*)(sy + jj);
            u64 pz = *(const u64*)(sz + jj);
            u64 pw = *(const u64*)(snw + jj);
            u64 dot2 = fma2(cz2, pz, fma2(cy2, py, mul2(cx2, px)));
            u64 pd2 = fma2(two2, dot2, add2(pw, bb2));   // bit-identical to phase 1
            float pl, ph; unpack2(pd2, pl, ph);
            if (pl >= v20f) {
                if (pl > v20f) { int p = atomicAdd(&ctrs[warp][0], 1); g_knn[base + p] = jj; }
                else { int p = atomicAdd(&ctrs[warp][1], 1); if (p < 16) eqbuf[warp][p] = jj; }
            }
            if (ph >= v20f) {
                if (ph > v20f) { int p = atomicAdd(&ctrs[warp][0], 1); g_knn[base + p] = jj + 1; }
                else { int p = atomicAdd(&ctrs[warp][1], 1); if (p < 16) eqbuf[warp][p] = jj + 1; }
            }
        }
        __syncwarp();
        int m = ctrs[warp][0], e = ctrs[warp][1];
        int need = KNNK - m;
        if (e == need) {                         // common: take all eq entries
            if (lane < need) g_knn[base + m + lane] = eqbuf[warp][lane];
        } else {                                 // rare value-tie at boundary:
            int myv = (lane < e && lane < 16) ? eqbuf[warp][lane] : 0x7FFFFFFF;
            #pragma unroll 1
            for (int t2 = 0; t2 < need; t2++) {  // smallest indices win (jax stable)
                unsigned mn = __reduce_min_sync(FULLMASK, (unsigned)myv);
                if ((unsigned)myv == mn) myv = 0x7FFFFFFF;
                if (lane == 0) g_knn[base + m + t2] = (int)mn;
            }
        }
        __syncwarp();
    }
}

// --- precompute: smem-staged xf tile; Ys = s1*(W1a xf), Ps = s1*((W1b-W1a) xf)+shift1 ---
__global__ __launch_bounds__(256) void pre_kernel(
    const float* __restrict__ xf, const float* __restrict__ W1,
    const float* __restrict__ g1, const float* __restrict__ b1,
    const float* __restrict__ m1, const float* __restrict__ v1) {
    __shared__ float W1T[128 * 32];   // [c][o] transposed for conflict-free LDS
    __shared__ float xtile[64][64];   // [c][nn]: 64 channels x 64 points, coalesced fill
    int bq = blockIdx.x >> 5;         // batch (32 blocks per batch)
    int n0 = (blockIdx.x & 31) * 64;  // first point of this block
    for (int i = threadIdx.x; i < 4096; i += 256) {
        int o = i & 31, cc = i >> 5;
        W1T[cc * 32 + o] = W1[o * 128 + cc];
    }
    const float* xfb = xf + (size_t)bq * 64 * NPT + n0;
    for (int i = threadIdx.x; i < 4096; i += 256) {
        int cc = i >> 6, nn = i & 63;
        xtile[cc][nn] = xfb[(size_t)cc * NPT + nn];   // coalesced 64-float rows
    }
    __syncthreads();
    int warp = threadIdx.x >> 5, lane = threadIdx.x & 31;
    float s = g1[lane] * rsqrtf(v1[lane] + EPSV);
    float shift = fmaf(-m1[lane], s, b1[lane]);
    #pragma unroll 1
    for (int pp = 0; pp < 8; pp++) {
        int nn = warp * 8 + pp;
        int point = bq * NPT + n0 + nn;
        float y = 0.f, p = 0.f;
        #pragma unroll
        for (int cc = 0; cc < 64; cc++) {
            float xv = xtile[cc][nn];               // smem broadcast
            float wa = W1T[cc * 32 + lane];         // W1[:,0:64]  (nbr - x part)
            float wb = W1T[(cc + 64) * 32 + lane];  // W1[:,64:128] (x part)
            y = fmaf(wa, xv, y);
            p = fmaf(wb - wa, xv, p);
        }
        g_Ys[point * 32 + lane] = y * s;
        g_Ps[point * 32 + lane] = fmaf(p, s, shift);
    }
}

// ---- edge MLP: warp per 4 points interleaved, LDS.128 broadcasts, FFMA2 GEMVs ----
__global__ __launch_bounds__(128) void mlp_kernel(
    const float* __restrict__ W2, const float* __restrict__ g2,
    const float* __restrict__ b2, const float* __restrict__ m2,
    const float* __restrict__ v2, const float* __restrict__ W3,
    float* __restrict__ out) {
    __shared__ float W2T[1024];   // [c][o], BN2 scale folded
    __shared__ float W3T[2048];   // [c][o]
    __shared__ float sh2s[32];
    __shared__ __align__(16) float hbuf[4][4][32];   // [warp][pt][lane]
    __shared__ __align__(16) float fbuf[4][4][32];
    for (int i = threadIdx.x; i < 1024; i += 128) {
        int o = i & 31, cc = i >> 5;
        float s2 = g2[o] * rsqrtf(v2[o] + EPSV);
        W2T[cc * 32 + o] = W2[o * 32 + cc] * s2;
    }
    for (int i = threadIdx.x; i < 2048; i += 128) {
        int o = i & 63, cc = i >> 6;
        W3T[cc * 64 + o] = W3[o * 32 + cc];
    }
    if (threadIdx.x < 32) {
        int o = threadIdx.x;
        float s2 = g2[o] * rsqrtf(v2[o] + EPSV);
        sh2s[o] = fmaf(-m2[o], s2, b2[o]);
    }
    __syncthreads();
    int warp = threadIdx.x >> 5, lane = threadIdx.x & 31;
    // pre-packed weight pairs (consecutive input channels -> f32x2 lanes)
    u64 w2p[16], w3ap[16], w3bp[16];
    #pragma unroll
    for (int q = 0; q < 16; q++) {
        w2p[q]  = pack2(W2T[(2 * q) * 32 + lane],      W2T[(2 * q + 1) * 32 + lane]);
        w3ap[q] = pack2(W3T[(2 * q) * 64 + lane],      W3T[(2 * q + 1) * 64 + lane]);
        w3bp[q] = pack2(W3T[(2 * q) * 64 + 32 + lane], W3T[(2 * q + 1) * 64 + 32 + lane]);
    }
    float sh2 = sh2s[lane];
    const float4* hb = (const float4*)hbuf[warp];   // pt u at hb + u*8
    const float4* fb = (const float4*)fbuf[warp];
    #pragma unroll 1
    for (int pp = 0; pp < 2; pp++) {
        int p0 = (blockIdx.x * 4 + warp) * 8 + 4 * pp;  // 4 consecutive points
        int b = p0 >> 11, n0 = p0 & (NPT - 1);
        const float* YsB = g_Ys + (size_t)b * NPT * 32;
        float ps[4], ysn[4];
        int idx[4];
        #pragma unroll
        for (int u = 0; u < 4; u++) {
            ps[u] = g_Ps[(p0 + u) * 32 + lane];
            idx[u] = (lane < KNNK) ? g_knn[(p0 + u) * KNNK + lane] : 0;
        }
        #pragma unroll
        for (int u = 0; u < 4; u++) {
            int j = __shfl_sync(FULLMASK, idx[u], 0);
            ysn[u] = YsB[j * 32 + lane];   // software-pipelined gathers
        }
        float a0[4], a1[4];
        #pragma unroll
        for (int u = 0; u < 4; u++) { a0[u] = NEGINF; a1[u] = NEGINF; }
        #pragma unroll 1
        for (int k = 0; k < KNNK; k++) {
            #pragma unroll
            for (int u = 0; u < 4; u++) {
                float h = ysn[u] + ps[u];
                if (k + 1 < KNNK) {
                    int jn = __shfl_sync(FULLMASK, idx[u], k + 1);
                    ysn[u] = YsB[jn * 32 + lane];
                }
                hbuf[warp][u][lane] = fmaxf(h, 0.2f * h);   // leaky relu
            }
            __syncwarp();
            u64 acc[4] = {0, 0, 0, 0};   // 4 independent chains
            #pragma unroll
            for (int q = 0; q < 8; q++) {
                #pragma unroll
                for (int u = 0; u < 4; u++) {
                    float4 hv = hb[u * 8 + q];
                    acc[u] = fma2(w2p[2 * q],     pack2(hv.x, hv.y), acc[u]);
                    acc[u] = fma2(w2p[2 * q + 1], pack2(hv.z, hv.w), acc[u]);
                }
            }
            #pragma unroll
            for (int u = 0; u < 4; u++) {
                float ax, ay;
                unpack2(acc[u], ax, ay);
                float f = ax + ay + sh2;
                fbuf[warp][u][lane] = fmaxf(f, 0.2f * f);
            }
            __syncwarp();
            u64 t0[4] = {0, 0, 0, 0}, t1[4] = {0, 0, 0, 0};  // 8 chains
            #pragma unroll
            for (int q = 0; q < 8; q++) {
                #pragma unroll
                for (int u = 0; u < 4; u++) {
                    float4 fv = fb[u * 8 + q];
                    u64 lo = pack2(fv.x, fv.y), hi = pack2(fv.z, fv.w);
                    t0[u] = fma2(w3ap[2 * q], lo, t0[u]);
                    t1[u] = fma2(w3bp[2 * q], lo, t1[u]);
                    t0[u] = fma2(w3ap[2 * q + 1], hi, t0[u]);
                    t1[u] = fma2(w3bp[2 * q + 1], hi, t1[u]);
                }
            }
            #pragma unroll
            for (int u = 0; u < 4; u++) {
                float x0, y0, x1, y1;
                unpack2(t0[u], x0, y0);
                unpack2(t1[u], x1, y1);
                a0[u] = fmaxf(a0[u], x0 + y0);
                a1[u] = fmaxf(a1[u], x1 + y1);
            }
        }
        // out[b][c][2n+u']: 4 adjacent points -> two 16B stores (n0 % 4 == 0)
        float* obase = out + (size_t)(b * 32 + lane) * (2 * NPT) + 2 * n0;
        ((float4*)obase)[0] = make_float4(a0[0], a1[0], a0[1], a1[1]);
        ((float4*)obase)[1] = make_float4(a0[2], a1[2], a0[3], a1[3]);
    }
}

extern "C" void kernel_launch(void* const* d_in, const int* in_sizes, int n_in,
                              void* d_out, int out_size) {
    const float* xyz = (const float*)d_in[0];
    const float* xf  = (const float*)d_in[1];
    const float* W1  = (const float*)d_in[2];
    const float* g1  = (const float*)d_in[3];
    const float* b1  = (const float*)d_in[4];
    const float* m1  = (const float*)d_in[5];
    const float* v1  = (const float*)d_in[6];
    const float* W2  = (const float*)d_in[7];
    const float* g2  = (const float*)d_in[8];
    const float* b2  = (const float*)d_in[9];
    const float* m2  = (const float*)d_in[10];
    const float* v2  = (const float*)d_in[11];
    const float* W3  = (const float*)d_in[12];
    float* out = (float*)d_out;

    knn_kernel<<<1024, 256>>>(xyz);
    pre_kernel<<<512, 256>>>(xf, W1, g1, b1, m1, v1);
    mlp_kernel<<<1024, 128>>>(W2, g2, b2, m2, v2, W3, out);
}

// round 14
// speedup vs baseline: 1.1570x; 1.0663x over previous
#include <cuda_runtime.h>
#include <stdint.h>

#define FULLMASK 0xFFFFFFFFu
#define NBATCH 16
#define NPT 2048
#define KNNK 20
#define EPSV 1e-5f
#define NEGINF (__int_as_float(0xff800000))

typedef unsigned long long u64;

// scratch (device globals: no allocation allowed)
__device__ float g_Ys[NBATCH * NPT * 32];
__device__ float g_Ps[NBATCH * NPT * 32];
__device__ int   g_knn[NBATCH * NPT * KNNK];

// ---- packed f32x2 helpers ----
__device__ __forceinline__ u64 pack2(float a, float b) {
    u64 r; asm("mov.b64 %0, {%1, %2};" : "=l"(r) : "f"(a), "f"(b)); return r;
}
__device__ __forceinline__ void unpack2(u64 v, float& a, float& b) {
    asm("mov.b64 {%0, %1}, %2;" : "=f"(a), "=f"(b) : "l"(v));
}
__device__ __forceinline__ u64 fma2(u64 a, u64 b, u64 c) {
    u64 d; asm("fma.rn.f32x2 %0, %1, %2, %3;" : "=l"(d) : "l"(a), "l"(b), "l"(c)); return d;
}
__device__ __forceinline__ u64 mul2(u64 a, u64 b) {
    u64 d; asm("mul.rn.f32x2 %0, %1, %2;" : "=l"(d) : "l"(a), "l"(b)); return d;
}
__device__ __forceinline__ u64 add2(u64 a, u64 b) {
    u64 d; asm("add.rn.f32x2 %0, %1, %2;" : "=l"(d) : "l"(a), "l"(b)); return d;
}

// monotone u32 transform of float (order-preserving)
__device__ __forceinline__ unsigned monot(float v) {
    unsigned u = __float_as_uint(v);
    return u ^ ((unsigned)(((int)u) >> 31) | 0x80000000u);
}

// values-only sorted-desc top-3 insert: pure min/max network (5 FMNMX)
__device__ __forceinline__ void ins3v(float& v1, float& v2, float& v3, float pd) {
    float u1 = fminf(v1, pd); v1 = fmaxf(v1, pd);
    float u2 = fminf(v2, u1); v2 = fmaxf(v2, u1);
    v3 = fmaxf(v3, u2);
}

// ---- KNN: warp/row. Phase1: value-only scan. Phase2: REDUX select v20.
//      Phase3: threshold collect with index recovery (order-free output). ----
__global__ __launch_bounds__(256) void knn_kernel(const float* __restrict__ xyz) {
    __shared__ __align__(16) float sx[NPT], sy[NPT], sz[NPT], snw[NPT];
    __shared__ int eqbuf[8][16];
    __shared__ int ctrs[8][2];   // [warp][0]=gt count, [1]=eq count
    int b = blockIdx.x >> 6;          // 64 blocks per batch
    int chunk = blockIdx.x & 63;      // 32 rows per block
    const float* xb = xyz + (size_t)b * 3 * NPT;
    for (int i = threadIdx.x; i < NPT; i += 256) {
        float x = xb[i], y = xb[NPT + i], z = xb[2 * NPT + i];
        sx[i] = x; sy[i] = y; sz[i] = z;
        snw[i] = -(x * x + y * y + z * z);
    }
    __syncthreads();
    int warp = threadIdx.x >> 5, lane = threadIdx.x & 31;
    const u64 two2 = pack2(2.0f, 2.0f);
    #pragma unroll 1
    for (int rr = 0; rr < 4; rr++) {
        int n = chunk * 32 + warp * 4 + rr;
        float cx = sx[n], cy = sy[n], cz = sz[n];
        u64 cx2 = pack2(cx, cx), cy2 = pack2(cy, cy), cz2 = pack2(cz, cz);
        u64 bb2 = pack2(snw[n], snw[n]);
        // ---- phase 1: values-only dual top-3 (even j -> A, odd j -> B) ----
        float va1 = NEGINF, va2 = NEGINF, va3 = NEGINF;
        float vb1 = NEGINF, vb2 = NEGINF, vb3 = NEGINF;
        #pragma unroll 4
        for (int t = 0; t < 32; t++) {
            int jj = t * 64 + 2 * lane;
            u64 px = *(const u64*)(sx + jj);
            u64 py = *(const u64*)(sy + jj);
            u64 pz = *(const u64*)(sz + jj);
            u64 pw = *(const u64*)(snw + jj);
            u64 dot2 = fma2(cz2, pz, fma2(cy2, py, mul2(cx2, px)));
            u64 pd2 = fma2(two2, dot2, add2(pw, bb2));  // 2*dot - xx_i - xx_j
            float pl, ph; unpack2(pd2, pl, ph);
            ins3v(va1, va2, va3, pl);
            ins3v(vb1, vb2, vb3, ph);
        }
        // ---- phase 2: 20 REDUX rounds -> v20f (20th largest, with multiplicity) ----
        float v20f = 0.f;
        #pragma unroll 1
        for (int r = 0; r < KNNK; r++) {
            float v1 = fmaxf(va1, vb1);
            unsigned key = monot(v1);
            unsigned mx = __reduce_max_sync(FULLMASK, key);
            unsigned ball = __ballot_sync(FULLMASK, key == mx);
            int wl = __ffs(ball) - 1;          // unique winner lane
            if (r == KNNK - 1) { v20f = __shfl_sync(FULLMASK, v1, wl); break; }
            bool win = (lane == wl);
            bool pA = (va1 >= vb1);
            bool popA = win && pA, popB = win && !pA;
            va1 = popA ? va2 : va1; va2 = popA ? va3 : va2; va3 = popA ? NEGINF : va3;
            vb1 = popB ? vb2 : vb1; vb2 = popB ? vb3 : vb2; vb3 = popB ? NEGINF : vb3;
            // refill a list when it empties: all its values > v1 already emitted
            if (popA && va1 == NEGINF) {   // ~2% of rows
                #pragma unroll 4
                for (int t = 0; t < 32; t++) {
                    int jj = t * 64 + 2 * lane;
                    u64 px = *(const u64*)(sx + jj);
                    u64 py = *(const u64*)(sy + jj);
                    u64 pz = *(const u64*)(sz + jj);
                    u64 pw = *(const u64*)(snw + jj);
                    u64 dot2 = fma2(cz2, pz, fma2(cy2, py, mul2(cx2, px)));
                    u64 pd2 = fma2(two2, dot2, add2(pw, bb2));
                    float pl, ph; unpack2(pd2, pl, ph);
                    (void)ph;
                    ins3v(va1, va2, va3, (pl < v1) ? pl : NEGINF);
                }
            }
            if (popB && vb1 == NEGINF) {
                #pragma unroll 4
                for (int t = 0; t < 32; t++) {
                    int jj = t * 64 + 2 * lane;
                    u64 px = *(const u64*)(sx + jj);
                    u64 py = *(const u64*)(sy + jj);
                    u64 pz = *(const u64*)(sz + jj);
                    u64 pw = *(const u64*)(snw + jj);
                    u64 dot2 = fma2(cz2, pz, fma2(cy2, py, mul2(cx2, px)));
                    u64 pd2 = fma2(two2, dot2, add2(pw, bb2));
                    float pl, ph; unpack2(pd2, pl, ph);
                    (void)pl;
                    ins3v(vb1, vb2, vb3, (ph < v1) ? ph : NEGINF);
                }
            }
        }
        // ---- phase 3: collect indices (order-free; jax tie rule at boundary) ----
        if (lane == 0) { ctrs[warp][0] = 0; ctrs[warp][1] = 0; }
        __syncwarp();
        int base = (b * NPT + n) * KNNK;
        #pragma unroll 4
        for (int t = 0; t < 32; t++) {
            int jj = t * 64 + 2 * lane;
            u64 px = *(const u64*)(sx + jj);
            u64 py = *(const u64*)(sy + jj);
            u64 pz = *(const u64*)(sz + jj);
            u64 pw = *(const u64*)(snw + jj);
            u64 dot2 = fma2(cz2, pz, fma2(cy2, py, mul2(cx2, px)));
            u64 pd2 = fma2(two2, dot2, add2(pw, bb2));   // bit-identical to phase 1
            float pl, ph; unpack2(pd2, pl, ph);
            if (pl >= v20f) {
                if (pl > v20f) { int p = atomicAdd(&ctrs[warp][0], 1); g_knn[base + p] = jj; }
                else { int p = atomicAdd(&ctrs[warp][1], 1); if (p < 16) eqbuf[warp][p] = jj; }
            }
            if (ph >= v20f) {
                if (ph > v20f) { int p = atomicAdd(&ctrs[warp][0], 1); g_knn[base + p] = jj + 1; }
                else { int p = atomicAdd(&ctrs[warp][1], 1); if (p < 16) eqbuf[warp][p] = jj + 1; }
            }
        }
        __syncwarp();
        int m = ctrs[warp][0], e = ctrs[warp][1];
        int need = KNNK - m;
        if (e == need) {                         // common: take all eq entries
            if (lane < need) g_knn[base + m + lane] = eqbuf[warp][lane];
        } else {                                 // rare value-tie at boundary:
            int myv = (lane < e && lane < 16) ? eqbuf[warp][lane] : 0x7FFFFFFF;
            #pragma unroll 1
            for (int t2 = 0; t2 < need; t2++) {  // smallest indices win (jax stable)
                unsigned mn = __reduce_min_sync(FULLMASK, (unsigned)myv);
                if ((unsigned)myv == mn) myv = 0x7FFFFFFF;
                if (lane == 0) g_knn[base + m + t2] = (int)mn;
            }
        }
        __syncwarp();
    }
}

// --- precompute (transposed): lane = point, 32 points/warp, coalesced LDG,
//     broadcast LDS.128 weights, 32 independent fma2 chains, smem-transposed output ---
__global__ __launch_bounds__(128) void pre_kernel(
    const float* __restrict__ xf, const float* __restrict__ W1,
    const float* __restrict__ g1, const float* __restrict__ b1,
    const float* __restrict__ m1, const float* __restrict__ v1) {
    __shared__ __align__(16) u64 sm[4096];   // 32KB: W1P (2048 u64) then reused as tiles
    __shared__ float shs[32];
    // W1P[cc][o] = (wa*s_o, (wb-wa)*s_o)
    for (int i = threadIdx.x; i < 2048; i += 128) {
        int o = i & 31, cc = i >> 5;
        float s = g1[o] * rsqrtf(v1[o] + EPSV);
        float wa = W1[o * 128 + cc], wb = W1[o * 128 + 64 + cc];
        sm[cc * 32 + o] = pack2(wa * s, (wb - wa) * s);
    }
    if (threadIdx.x < 32) {
        int o = threadIdx.x;
        float s = g1[o] * rsqrtf(v1[o] + EPSV);
        shs[o] = fmaf(-m1[o], s, b1[o]);
    }
    __syncthreads();
    int warp = threadIdx.x >> 5, lane = threadIdx.x & 31;
    int n = (blockIdx.x * 4 + warp) * 32 + lane;   // my point
    int b = n >> 11, nn = n & (NPT - 1);
    const float* col = xf + (size_t)b * 64 * NPT + nn;
    float xv[64];
    #pragma unroll
    for (int cc = 0; cc < 64; cc++) xv[cc] = col[(size_t)cc * NPT];   // coalesced
    u64 acc[32];
    #pragma unroll
    for (int o = 0; o < 32; o++) acc[o] = 0;
    #pragma unroll 4
    for (int cc = 0; cc < 64; cc++) {
        u64 x2 = pack2(xv[cc], xv[cc]);
        const ulonglong2* wrow = (const ulonglong2*)(sm + cc * 32);
        #pragma unroll
        for (int j = 0; j < 16; j++) {
            ulonglong2 w = wrow[j];    // LDS.128 broadcast: weights for o=2j, 2j+1
            acc[2 * j]     = fma2(w.x, x2, acc[2 * j]);
            acc[2 * j + 1] = fma2(w.y, x2, acc[2 * j + 1]);
        }
    }
    __syncthreads();   // everyone done reading W1P; reuse sm as transpose tiles
    u64* tile = sm + warp * 1024;   // [point][o^point] XOR-swizzled, 8KB per warp
    #pragma unroll
    for (int o = 0; o < 32; o++)
        tile[lane * 32 + (o ^ lane)] = acc[o];
    __syncwarp();
    float sh = shs[lane];
    int n0 = (blockIdx.x * 4 + warp) * 32;
    #pragma unroll
    for (int p = 0; p < 32; p++) {
        u64 v = tile[p * 32 + (lane ^ p)];   // conflict-free: permutation within row
        float y, pq; unpack2(v, y, pq);
        g_Ys[(size_t)(n0 + p) * 32 + lane] = y;         // coalesced
        g_Ps[(size_t)(n0 + p) * 32 + lane] = pq + sh;   // coalesced
    }
}

// ---- edge MLP: warp per 4 points interleaved, LDS.128 broadcasts, FFMA2 GEMVs ----
__global__ __launch_bounds__(128) void mlp_kernel(
    const float* __restrict__ W2, const float* __restrict__ g2,
    const float* __restrict__ b2, const float* __restrict__ m2,
    const float* __restrict__ v2, const float* __restrict__ W3,
    float* __restrict__ out) {
    __shared__ float W2T[1024];   // [c][o], BN2 scale folded
    __shared__ float W3T[2048];   // [c][o]
    __shared__ float sh2s[32];
    __shared__ __align__(16) float hbuf[4][4][32];   // [warp][pt][lane]
    __shared__ __align__(16) float fbuf[4][4][32];
    for (int i = threadIdx.x; i < 1024; i += 128) {
        int o = i & 31, cc = i >> 5;
        float s2 = g2[o] * rsqrtf(v2[o] + EPSV);
        W2T[cc * 32 + o] = W2[o * 32 + cc] * s2;
    }
    for (int i = threadIdx.x; i < 2048; i += 128) {
        int o = i & 63, cc = i >> 6;
        W3T[cc * 64 + o] = W3[o * 32 + cc];
    }
    if (threadIdx.x < 32) {
        int o = threadIdx.x;
        float s2 = g2[o] * rsqrtf(v2[o] + EPSV);
        sh2s[o] = fmaf(-m2[o], s2, b2[o]);
    }
    __syncthreads();
    int warp = threadIdx.x >> 5, lane = threadIdx.x & 31;
    // pre-packed weight pairs (consecutive input channels -> f32x2 lanes)
    u64 w2p[16], w3ap[16], w3bp[16];
    #pragma unroll
    for (int q = 0; q < 16; q++) {
        w2p[q]  = pack2(W2T[(2 * q) * 32 + lane],      W2T[(2 * q + 1) * 32 + lane]);
        w3ap[q] = pack2(W3T[(2 * q) * 64 + lane],      W3T[(2 * q + 1) * 64 + lane]);
        w3bp[q] = pack2(W3T[(2 * q) * 64 + 32 + lane], W3T[(2 * q + 1) * 64 + 32 + lane]);
    }
    float sh2 = sh2s[lane];
    const float4* hb = (const float4*)hbuf[warp];   // pt u at hb + u*8
    const float4* fb = (const float4*)fbuf[warp];
    #pragma unroll 1
    for (int pp = 0; pp < 2; pp++) {
        int p0 = (blockIdx.x * 4 + warp) * 8 + 4 * pp;  // 4 consecutive points
        int b = p0 >> 11, n0 = p0 & (NPT - 1);
        const float* YsB = g_Ys + (size_t)b * NPT * 32;
        float ps[4], ysn[4];
        int idx[4];
        #pragma unroll
        for (int u = 0; u < 4; u++) {
            ps[u] = g_Ps[(p0 + u) * 32 + lane];
            idx[u] = (lane < KNNK) ? g_knn[(p0 + u) * KNNK + lane] : 0;
        }
        #pragma unroll
        for (int u = 0; u < 4; u++) {
            int j = __shfl_sync(FULLMASK, idx[u], 0);
            ysn[u] = YsB[j * 32 + lane];   // software-pipelined gathers
        }
        float a0[4], a1[4];
        #pragma unroll
        for (int u = 0; u < 4; u++) { a0[u] = NEGINF; a1[u] = NEGINF; }
        #pragma unroll 1
        for (int k = 0; k < KNNK; k++) {
            #pragma unroll
            for (int u = 0; u < 4; u++) {
                float h = ysn[u] + ps[u];
                if (k + 1 < KNNK) {
                    int jn = __shfl_sync(FULLMASK, idx[u], k + 1);
                    ysn[u] = YsB[jn * 32 + lane];
                }
                hbuf[warp][u][lane] = fmaxf(h, 0.2f * h);   // leaky relu
            }
            __syncwarp();
            u64 acc[4] = {0, 0, 0, 0};   // 4 independent chains
            #pragma unroll
            for (int q = 0; q < 8; q++) {
                #pragma unroll
                for (int u = 0; u < 4; u++) {
                    float4 hv = hb[u * 8 + q];
                    acc[u] = fma2(w2p[2 * q],     pack2(hv.x, hv.y), acc[u]);
                    acc[u] = fma2(w2p[2 * q + 1], pack2(hv.z, hv.w), acc[u]);
                }
            }
            #pragma unroll
            for (int u = 0; u < 4; u++) {
                float ax, ay;
                unpack2(acc[u], ax, ay);
                float f = ax + ay + sh2;
                fbuf[warp][u][lane] = fmaxf(f, 0.2f * f);
            }
            __syncwarp();
            u64 t0[4] = {0, 0, 0, 0}, t1[4] = {0, 0, 0, 0};  // 8 chains
            #pragma unroll
            for (int q = 0; q < 8; q++) {
                #pragma unroll
                for (int u = 0; u < 4; u++) {
                    float4 fv = fb[u * 8 + q];
                    u64 lo = pack2(fv.x, fv.y), hi = pack2(fv.z, fv.w);
                    t0[u] = fma2(w3ap[2 * q], lo, t0[u]);
                    t1[u] = fma2(w3bp[2 * q], lo, t1[u]);
                    t0[u] = fma2(w3ap[2 * q + 1], hi, t0[u]);
                    t1[u] = fma2(w3bp[2 * q + 1], hi, t1[u]);
                }
            }
            #pragma unroll
            for (int u = 0; u < 4; u++) {
                float x0, y0, x1, y1;
                unpack2(t0[u], x0, y0);
                unpack2(t1[u], x1, y1);
                a0[u] = fmaxf(a0[u], x0 + y0);
                a1[u] = fmaxf(a1[u], x1 + y1);
            }
        }
        // out[b][c][2n+u']: 4 adjacent points -> two 16B stores (n0 % 4 == 0)
        float* obase = out + (size_t)(b * 32 + lane) * (2 * NPT) + 2 * n0;
        ((float4*)obase)[0] = make_float4(a0[0], a1[0], a0[1], a1[1]);
        ((float4*)obase)[1] = make_float4(a0[2], a1[2], a0[3], a1[3]);
    }
}

extern "C" void kernel_launch(void* const* d_in, const int* in_sizes, int n_in,
                              void* d_out, int out_size) {
    const float* xyz = (const float*)d_in[0];
    const float* xf  = (const float*)d_in[1];
    const float* W1  = (const float*)d_in[2];
    const float* g1  = (const float*)d_in[3];
    const float* b1  = (const float*)d_in[4];
    const float* m1  = (const float*)d_in[5];
    const float* v1  = (const float*)d_in[6];
    const float* W2  = (const float*)d_in[7];
    const float* g2  = (const float*)d_in[8];
    const float* b2  = (const float*)d_in[9];
    const float* m2  = (const float*)d_in[10];
    const float* v2  = (const float*)d_in[11];
    const float* W3  = (const float*)d_in[12];
    float* out = (float*)d_out;

    knn_kernel<<<1024, 256>>>(xyz);
    pre_kernel<<<256, 128>>>(xf, W1, g1, b1, m1, v1);
    mlp_kernel<<<1024, 128>>>(W2, g2, b2, m2, v2, W3, out);
}